// round 13
// baseline (speedup 1.0000x reference)
#include <cuda_runtime.h>
#include <stdint.h>

#define B_  32
#define H_  512
#define W_  512
#define PIX_PER_IMG (H_ * W_)                    // 262144
#define CHUNKS 64                                // moments blocks per batch
#define F4_PER_CHUNK (PIX_PER_IMG / CHUNKS / 4)  // 1024 float4 per block
#define F4_PER_THREAD (F4_PER_CHUNK / 256)       // 4 (front-batched, MLP_p1=4)
#define SHIFT_ELEMS 8
#define FP_SCALE 1048576.0f                      // 2^20 (exact float scaling)

// Scratch (no allocations allowed) — zero-init; self-reset every launch.
__device__ long long    g_tot[B_ * 3];   // fixed-point (m00,m10,m01) per batch
__device__ int          g_shift[B_ * 2]; // (dx, dy) ints per batch
__device__ unsigned int g_cnt[B_];       // per-batch arrival counters

// ---------------------------------------------------------------------------
// Stage 1: mk moments. Block partials reduced deterministically (butterfly +
// fixed-order smem sum), committed as 2^20 fixed-point via integer atomicAdd
// (associative -> deterministic totals regardless of arrival order).
// The 64th arrival per batch converts totals to (dx,dy) ints — 2 double
// divides per BATCH — and self-resets the scratch for graph replay.
// ---------------------------------------------------------------------------
__global__ __launch_bounds__(256) void moments_kernel(const float* __restrict__ mk)
{
    const int b     = blockIdx.y;
    const int chunk = blockIdx.x;       // 0..63
    const int t     = threadIdx.x;      // 0..255
    const int lane  = t & 31;
    const int wid   = t >> 5;           // 0..7

    const float4* base =
        (const float4*)(mk + (size_t)b * PIX_PER_IMG) + chunk * F4_PER_CHUNK;

    // Front-batch all 4 independent loads (MLP_p1=4).
    float4 v[F4_PER_THREAD];
#pragma unroll
    for (int i = 0; i < F4_PER_THREAD; i++)
        v[i] = base[t + i * 256];

    float s0 = 0.f, s1 = 0.f, s2 = 0.f;
#pragma unroll
    for (int i = 0; i < F4_PER_THREAD; i++) {
        const int p = chunk * (F4_PER_CHUNK * 4) + (t + i * 256) * 4;
        const int h = p >> 9;
        const int w = p & (W_ - 1);
        const float ry  = (float)(h - (H_ / 2));
        const float rx0 = (float)(w - (W_ / 2));
        const float sum = v[i].x + v[i].y + v[i].z + v[i].w;
        s0 += sum;
        s2 += ry * sum;
        s1 += rx0 * v[i].x + (rx0 + 1.f) * v[i].y + (rx0 + 2.f) * v[i].z
            + (rx0 + 3.f) * v[i].w;
    }

    // Warp butterfly reduce (deterministic fixed order)
#pragma unroll
    for (int m = 16; m > 0; m >>= 1) {
        s0 += __shfl_xor_sync(0xffffffffu, s0, m);
        s1 += __shfl_xor_sync(0xffffffffu, s1, m);
        s2 += __shfl_xor_sync(0xffffffffu, s2, m);
    }

    __shared__ float w0[8], w1[8], w2[8];
    if (lane == 0) { w0[wid] = s0; w1[wid] = s1; w2[wid] = s2; }
    __syncthreads();

    if (t == 0) {
        float r0 = 0.f, r1 = 0.f, r2 = 0.f;
#pragma unroll
        for (int i = 0; i < 8; i++) { r0 += w0[i]; r1 += w1[i]; r2 += w2[i]; }
        // Exact *2^20 scaling; llrintf error <= 0.5 fixed units per block.
        atomicAdd((unsigned long long*)&g_tot[b * 3 + 0],
                  (unsigned long long)llrintf(r0 * FP_SCALE));
        atomicAdd((unsigned long long*)&g_tot[b * 3 + 1],
                  (unsigned long long)llrintf(r1 * FP_SCALE));
        atomicAdd((unsigned long long*)&g_tot[b * 3 + 2],
                  (unsigned long long)llrintf(r2 * FP_SCALE));
        __threadfence();   // totals commit ordered before the arrival tick

        if (atomicAdd(&g_cnt[b], 1u) == CHUNKS - 1) {
            // All 64 commits for batch b are visible (each preceded its tick).
            // Read via atomic RMW(+0) to bypass any stale L1 line.
            const long long t0v = (long long)atomicAdd(
                (unsigned long long*)&g_tot[b * 3 + 0], 0ull);
            const long long t1v = (long long)atomicAdd(
                (unsigned long long*)&g_tot[b * 3 + 1], 0ull);
            const long long t2v = (long long)atomicAdd(
                (unsigned long long*)&g_tot[b * 3 + 2], 0ull);
            const double den = fmax(1048.576, (double)t0v);  // 0.001*2^20 floor
            // rint = round-half-even, matching jnp.round
            g_shift[b * 2 + 0] = (int)rint((double)t1v / den);   // dx
            g_shift[b * 2 + 1] = (int)rint((double)t2v / den);   // dy
            // Self-reset for next graph replay (only this block touches these
            // again this launch; shift kernel reads only g_shift).
            g_tot[b * 3 + 0] = 0ll;
            g_tot[b * 3 + 1] = 0ll;
            g_tot[b * 3 + 2] = 0ll;
            g_cnt[b] = 0u;
            __threadfence();
        }
    }
}

// ---------------------------------------------------------------------------
// Stage 2: shifted copy (exact best-measured config: 37.6us).
// 8 pixels (8x float4) per thread; independent loads front-batched (MLP=8).
// out[b,h,w] = x[b, h+dy, w+dx] if in-bounds else 0   (clamped-pad semantics)
// ---------------------------------------------------------------------------
__global__ __launch_bounds__(256) void shift_kernel(const float4* __restrict__ x,
                                                    float4* __restrict__ out)
{
    const int b    = blockIdx.y;
    const int base = blockIdx.x * (256 * SHIFT_ELEMS);   // pixel base in image
    const int t    = threadIdx.x;

    const int dx = g_shift[b * 2 + 0];
    const int dy = g_shift[b * 2 + 1];

    const float4* xb = x + ((size_t)b << 18);
    float4* ob       = out + ((size_t)b << 18);

    float4 v[SHIFT_ELEMS];
#pragma unroll
    for (int k = 0; k < SHIFT_ELEMS; k++) {
        const int p = base + k * 256 + t;
        const int h = p >> 9;
        const int w = p & (W_ - 1);
        const int sh = h + dy;
        const int sw = w + dx;
        v[k] = make_float4(0.f, 0.f, 0.f, 0.f);
        if ((unsigned)sh < (unsigned)H_ && (unsigned)sw < (unsigned)W_)
            v[k] = xb[(sh << 9) + sw];
    }
#pragma unroll
    for (int k = 0; k < SHIFT_ELEMS; k++)
        ob[base + k * 256 + t] = v[k];
}

// ---------------------------------------------------------------------------
extern "C" void kernel_launch(void* const* d_in, const int* in_sizes, int n_in,
                              void* d_out, int out_size)
{
    const float* x  = (const float*)d_in[0];   // [32,512,512,4]
    const float* mk = (const float*)d_in[1];   // [32,512,512,1]

    dim3 g1(CHUNKS, B_);                       // (64, 32) = 2048 blocks
    moments_kernel<<<g1, 256>>>(mk);

    dim3 g2(PIX_PER_IMG / (256 * SHIFT_ELEMS), B_);   // (128, 32)
    shift_kernel<<<g2, 256>>>((const float4*)x, (float4*)d_out);
}

// round 14
// speedup vs baseline: 1.0792x; 1.0792x over previous
#include <cuda_runtime.h>
#include <stdint.h>

#define B_  32
#define H_  512
#define W_  512
#define PIX_PER_IMG (H_ * W_)                    // 262144
#define CHUNKS 64                                // moments blocks per batch
#define MBLK (B_ * CHUNKS)                       // 2048 moments blocks
#define F4_PER_CHUNK (PIX_PER_IMG / CHUNKS / 4)  // 1024 float4 per block
#define F4_PER_THREAD (F4_PER_CHUNK / 256)       // 4 (front-batched)
#define SHIFT_ELEMS 8
#define SBLK_PER_B (PIX_PER_IMG / (256 * SHIFT_ELEMS))   // 128
#define SBLK (B_ * SBLK_PER_B)                   // 4096 shift blocks
#define GRID_TOTAL (MBLK + SBLK)                 // 6144
#define FP_SCALE 1048576.0f                      // 2^20 (exact float scaling)

// Scratch (no allocations allowed) — zero-init; self-reset every launch.
__device__ long long    g_tot[B_ * 3];    // fixed-point (m00,m10,m01) per batch
__device__ int          g_shift[B_ * 2];  // (dx, dy) ints per batch
__device__ unsigned int g_cnt[B_];        // moments arrival counters
__device__ unsigned int g_ready[B_];      // per-batch release flags
__device__ unsigned int g_done;           // global completion counter

// ---------------------------------------------------------------------------
// Single launch, two block roles.
// Moments blocks (bid < 2048, scheduled first): R12-proven path — butterfly-
//   reduced partials committed as associative fixed-point atomics; 64th
//   arrival per batch does 2 double divides, publishes (dx,dy), releases flag.
// Shift blocks (bid >= 2048): front-issue ALL x loads at shift-independent
//   addresses (scatter formulation), THEN gate on the batch flag, then
//   scatter-store + zero the disjoint border complement.
//   out[h-dy, w-dx] = x[h,w] covers exactly the in-bounds-source out pixels;
//   out[p] = 0 where (h+dy) or (w+dx) leaves [0,512) covers the rest.
// ---------------------------------------------------------------------------
__global__ __launch_bounds__(256)
void fused_kernel(const float4* __restrict__ x,
                  const float*  __restrict__ mk,
                  float4* __restrict__ out)
{
    const int bid  = blockIdx.x;
    const int t    = threadIdx.x;
    const int lane = t & 31;
    const int wid  = t >> 5;

    if (bid < MBLK) {
        // =================== Moments role ===================
        const int b     = bid >> 6;          // 0..31
        const int chunk = bid & (CHUNKS - 1);

        const float4* base =
            (const float4*)(mk + (size_t)b * PIX_PER_IMG) + chunk * F4_PER_CHUNK;

        float4 v[F4_PER_THREAD];
#pragma unroll
        for (int i = 0; i < F4_PER_THREAD; i++)
            v[i] = base[t + i * 256];

        float s0 = 0.f, s1 = 0.f, s2 = 0.f;
#pragma unroll
        for (int i = 0; i < F4_PER_THREAD; i++) {
            const int p = chunk * (F4_PER_CHUNK * 4) + (t + i * 256) * 4;
            const int h = p >> 9;
            const int w = p & (W_ - 1);
            const float ry  = (float)(h - (H_ / 2));
            const float rx0 = (float)(w - (W_ / 2));
            const float sum = v[i].x + v[i].y + v[i].z + v[i].w;
            s0 += sum;
            s2 += ry * sum;
            s1 += rx0 * v[i].x + (rx0 + 1.f) * v[i].y + (rx0 + 2.f) * v[i].z
                + (rx0 + 3.f) * v[i].w;
        }

#pragma unroll
        for (int m = 16; m > 0; m >>= 1) {
            s0 += __shfl_xor_sync(0xffffffffu, s0, m);
            s1 += __shfl_xor_sync(0xffffffffu, s1, m);
            s2 += __shfl_xor_sync(0xffffffffu, s2, m);
        }

        __shared__ float w0[8], w1[8], w2[8];
        if (lane == 0) { w0[wid] = s0; w1[wid] = s1; w2[wid] = s2; }
        __syncthreads();

        if (t == 0) {
            float r0 = 0.f, r1 = 0.f, r2 = 0.f;
#pragma unroll
            for (int i = 0; i < 8; i++) { r0 += w0[i]; r1 += w1[i]; r2 += w2[i]; }
            atomicAdd((unsigned long long*)&g_tot[b * 3 + 0],
                      (unsigned long long)llrintf(r0 * FP_SCALE));
            atomicAdd((unsigned long long*)&g_tot[b * 3 + 1],
                      (unsigned long long)llrintf(r1 * FP_SCALE));
            atomicAdd((unsigned long long*)&g_tot[b * 3 + 2],
                      (unsigned long long)llrintf(r2 * FP_SCALE));
            __threadfence();

            if (atomicAdd(&g_cnt[b], 1u) == CHUNKS - 1) {
                const long long t0v = (long long)atomicAdd(
                    (unsigned long long*)&g_tot[b * 3 + 0], 0ull);
                const long long t1v = (long long)atomicAdd(
                    (unsigned long long*)&g_tot[b * 3 + 1], 0ull);
                const long long t2v = (long long)atomicAdd(
                    (unsigned long long*)&g_tot[b * 3 + 2], 0ull);
                const double den = fmax(1048.576, (double)t0v);  // 0.001*2^20
                // rint = round-half-even, matching jnp.round
                g_shift[b * 2 + 0] = (int)rint((double)t1v / den);   // dx
                g_shift[b * 2 + 1] = (int)rint((double)t2v / den);   // dy
                g_tot[b * 3 + 0] = 0ll;
                g_tot[b * 3 + 1] = 0ll;
                g_tot[b * 3 + 2] = 0ll;
                g_cnt[b] = 0u;
                __threadfence();                 // publish g_shift before flag
                atomicExch(&g_ready[b], 1u);
            }
        }
    } else {
        // =================== Shift role ===================
        const int sb    = bid - MBLK;
        const int b     = sb >> 7;               // batch
        const int chunk = sb & (SBLK_PER_B - 1);
        const int base  = chunk * (256 * SHIFT_ELEMS);

        const float4* xb = x + ((size_t)b << 18);
        float4* ob       = out + ((size_t)b << 18);

        // Front-issue ALL loads at shift-independent addresses (MLP=8).
        float4 v[SHIFT_ELEMS];
#pragma unroll
        for (int k = 0; k < SHIFT_ELEMS; k++)
            v[k] = xb[base + k * 256 + t];

        // Gate on batch readiness; loads above remain in flight meanwhile.
        __shared__ int s_dx, s_dy;
        if (t == 0) {
            while (atomicAdd(&g_ready[b], 0u) == 0u) __nanosleep(64);
            s_dx = atomicAdd(&((int*)g_shift)[b * 2 + 0], 0);
            s_dy = atomicAdd(&((int*)g_shift)[b * 2 + 1], 0);
        }
        __syncthreads();
        const int dx = s_dx;
        const int dy = s_dy;

#pragma unroll
        for (int k = 0; k < SHIFT_ELEMS; k++) {
            const int p = base + k * 256 + t;    // source pixel (x coords)
            const int h = p >> 9;
            const int w = p & (W_ - 1);
            // Scatter: out[h-dy, w-dx] = x[h, w] when target in bounds.
            const int th = h - dy;
            const int tw = w - dx;
            if ((unsigned)th < (unsigned)H_ && (unsigned)tw < (unsigned)W_)
                ob[(th << 9) + tw] = v[k];
            // Border complement: out[p] = 0 when its source is out of bounds.
            const int sh = h + dy;
            const int sw = w + dx;
            if ((unsigned)sh >= (unsigned)H_ || (unsigned)sw >= (unsigned)W_)
                ob[p] = make_float4(0.f, 0.f, 0.f, 0.f);
        }
    }

    // ---- Replay cleanup: last block overall resets the flags. Every shift
    // block has passed its gate before incrementing, so no one is stranded.
    __syncthreads();
    if (t == 0) {
        if (atomicAdd(&g_done, 1u) == GRID_TOTAL - 1) {
#pragma unroll
            for (int i = 0; i < B_; i++) g_ready[i] = 0u;
            g_done = 0u;
            __threadfence();
        }
    }
}

// ---------------------------------------------------------------------------
extern "C" void kernel_launch(void* const* d_in, const int* in_sizes, int n_in,
                              void* d_out, int out_size)
{
    const float* x  = (const float*)d_in[0];   // [32,512,512,4]
    const float* mk = (const float*)d_in[1];   // [32,512,512,1]

    fused_kernel<<<GRID_TOTAL, 256>>>((const float4*)x, mk, (float4*)d_out);
}

// round 15
// speedup vs baseline: 1.0893x; 1.0094x over previous
#include <cuda_runtime.h>
#include <stdint.h>

#define B_  32
#define H_  512
#define W_  512
#define PIX_PER_IMG (H_ * W_)                    // 262144
#define CHUNKS 32                                // moments blocks per batch
#define MBLK (B_ * CHUNKS)                       // 1024 moments blocks
#define F4_PER_CHUNK (PIX_PER_IMG / CHUNKS / 4)  // 2048 float4 per block
#define F4_PER_THREAD (F4_PER_CHUNK / 256)       // 8 (front-batched)
#define SHIFT_ELEMS 8
#define SBLK_PER_B (PIX_PER_IMG / (256 * SHIFT_ELEMS))   // 128
#define SBLK (B_ * SBLK_PER_B)                   // 4096 shift blocks
#define GRID_TOTAL (MBLK + SBLK)                 // 5120
#define FP_SCALE 1048576.0f                      // 2^20 (exact float scaling)

// Scratch (no allocations allowed) — zero-init; self-reset every launch.
__device__ long long    g_tot[B_ * 3];    // fixed-point (m00,m10,m01) per batch
__device__ int          g_shift[B_ * 2];  // (dx, dy) ints per batch
__device__ unsigned int g_cnt[B_];        // moments arrival counters
__device__ unsigned int g_ready[B_];      // per-batch release flags
__device__ unsigned int g_done;           // global completion counter

// ---------------------------------------------------------------------------
// Single launch, two block roles (R13 structure, tuned).
// Moments blocks (bid < 1024, scheduled first): butterfly-reduced partials
//   committed as associative fixed-point atomics; 32nd arrival per batch
//   does 2 double divides, publishes (dx,dy), releases the batch flag.
// Shift blocks (bid >= 1024): front-issue ALL x loads at shift-independent
//   addresses (scatter formulation), THEN gate on the batch flag, then
//   scatter-store + zero the disjoint border complement.
// __launch_bounds__(256,6): <=40 regs -> 6 blocks/SM (wave=888 covers all
//   1024 moments blocks within ~1.2 waves; shift blocks overlap the tail).
// ---------------------------------------------------------------------------
__global__ __launch_bounds__(256, 6)
void fused_kernel(const float4* __restrict__ x,
                  const float*  __restrict__ mk,
                  float4* __restrict__ out)
{
    const int bid  = blockIdx.x;
    const int t    = threadIdx.x;
    const int lane = t & 31;
    const int wid  = t >> 5;

    if (bid < MBLK) {
        // =================== Moments role ===================
        const int b     = bid >> 5;          // 0..31
        const int chunk = bid & (CHUNKS - 1);

        const float4* base =
            (const float4*)(mk + (size_t)b * PIX_PER_IMG) + chunk * F4_PER_CHUNK;

        float4 v[F4_PER_THREAD];
#pragma unroll
        for (int i = 0; i < F4_PER_THREAD; i++)
            v[i] = base[t + i * 256];

        float s0 = 0.f, s1 = 0.f, s2 = 0.f;
#pragma unroll
        for (int i = 0; i < F4_PER_THREAD; i++) {
            const int p = chunk * (F4_PER_CHUNK * 4) + (t + i * 256) * 4;
            const int h = p >> 9;
            const int w = p & (W_ - 1);
            const float ry  = (float)(h - (H_ / 2));
            const float rx0 = (float)(w - (W_ / 2));
            const float sum = v[i].x + v[i].y + v[i].z + v[i].w;
            s0 += sum;
            s2 += ry * sum;
            s1 += rx0 * v[i].x + (rx0 + 1.f) * v[i].y + (rx0 + 2.f) * v[i].z
                + (rx0 + 3.f) * v[i].w;
        }

#pragma unroll
        for (int m = 16; m > 0; m >>= 1) {
            s0 += __shfl_xor_sync(0xffffffffu, s0, m);
            s1 += __shfl_xor_sync(0xffffffffu, s1, m);
            s2 += __shfl_xor_sync(0xffffffffu, s2, m);
        }

        __shared__ float w0[8], w1[8], w2[8];
        if (lane == 0) { w0[wid] = s0; w1[wid] = s1; w2[wid] = s2; }
        __syncthreads();

        if (t == 0) {
            float r0 = 0.f, r1 = 0.f, r2 = 0.f;
#pragma unroll
            for (int i = 0; i < 8; i++) { r0 += w0[i]; r1 += w1[i]; r2 += w2[i]; }
            atomicAdd((unsigned long long*)&g_tot[b * 3 + 0],
                      (unsigned long long)llrintf(r0 * FP_SCALE));
            atomicAdd((unsigned long long*)&g_tot[b * 3 + 1],
                      (unsigned long long)llrintf(r1 * FP_SCALE));
            atomicAdd((unsigned long long*)&g_tot[b * 3 + 2],
                      (unsigned long long)llrintf(r2 * FP_SCALE));
            __threadfence();

            if (atomicAdd(&g_cnt[b], 1u) == CHUNKS - 1) {
                const long long t0v = (long long)atomicAdd(
                    (unsigned long long*)&g_tot[b * 3 + 0], 0ull);
                const long long t1v = (long long)atomicAdd(
                    (unsigned long long*)&g_tot[b * 3 + 1], 0ull);
                const long long t2v = (long long)atomicAdd(
                    (unsigned long long*)&g_tot[b * 3 + 2], 0ull);
                const double den = fmax(1048.576, (double)t0v);  // 0.001*2^20
                // rint = round-half-even, matching jnp.round
                g_shift[b * 2 + 0] = (int)rint((double)t1v / den);   // dx
                g_shift[b * 2 + 1] = (int)rint((double)t2v / den);   // dy
                g_tot[b * 3 + 0] = 0ll;
                g_tot[b * 3 + 1] = 0ll;
                g_tot[b * 3 + 2] = 0ll;
                g_cnt[b] = 0u;
                __threadfence();                 // publish g_shift before flag
                atomicExch(&g_ready[b], 1u);
            }
        }
    } else {
        // =================== Shift role ===================
        const int sb    = bid - MBLK;
        const int b     = sb >> 7;               // batch
        const int chunk = sb & (SBLK_PER_B - 1);
        const int base  = chunk * (256 * SHIFT_ELEMS);

        const float4* xb = x + ((size_t)b << 18);
        float4* ob       = out + ((size_t)b << 18);

        // Front-issue ALL loads at shift-independent addresses (MLP=8).
        float4 v[SHIFT_ELEMS];
#pragma unroll
        for (int k = 0; k < SHIFT_ELEMS; k++)
            v[k] = xb[base + k * 256 + t];

        // Gate on batch readiness; loads above remain in flight meanwhile.
        __shared__ int s_dx, s_dy;
        if (t == 0) {
            while (atomicAdd(&g_ready[b], 0u) == 0u) __nanosleep(64);
            s_dx = atomicAdd(&((int*)g_shift)[b * 2 + 0], 0);
            s_dy = atomicAdd(&((int*)g_shift)[b * 2 + 1], 0);
        }
        __syncthreads();
        const int dx = s_dx;
        const int dy = s_dy;

#pragma unroll
        for (int k = 0; k < SHIFT_ELEMS; k++) {
            const int p = base + k * 256 + t;    // source pixel (x coords)
            const int h = p >> 9;
            const int w = p & (W_ - 1);
            // Scatter: out[h-dy, w-dx] = x[h, w] when target in bounds.
            const int th = h - dy;
            const int tw = w - dx;
            if ((unsigned)th < (unsigned)H_ && (unsigned)tw < (unsigned)W_)
                ob[(th << 9) + tw] = v[k];
            // Border complement: out[p] = 0 when its source is out of bounds.
            const int sh = h + dy;
            const int sw = w + dx;
            if ((unsigned)sh >= (unsigned)H_ || (unsigned)sw >= (unsigned)W_)
                ob[p] = make_float4(0.f, 0.f, 0.f, 0.f);
        }
    }

    // ---- Replay cleanup: last block overall resets the flags. Every shift
    // block has passed its gate before incrementing, so no one is stranded.
    __syncthreads();
    if (t == 0) {
        if (atomicAdd(&g_done, 1u) == GRID_TOTAL - 1) {
#pragma unroll
            for (int i = 0; i < B_; i++) g_ready[i] = 0u;
            g_done = 0u;
            __threadfence();
        }
    }
}

// ---------------------------------------------------------------------------
extern "C" void kernel_launch(void* const* d_in, const int* in_sizes, int n_in,
                              void* d_out, int out_size)
{
    const float* x  = (const float*)d_in[0];   // [32,512,512,4]
    const float* mk = (const float*)d_in[1];   // [32,512,512,1]

    fused_kernel<<<GRID_TOTAL, 256>>>((const float4*)x, mk, (float4*)d_out);
}